// round 17
// baseline (speedup 1.0000x reference)
#include <cuda_runtime.h>
#include <cuda_fp16.h>

// SimpleRNN: 2-layer tanh RNN, B=8192, S=512, H=16, INPUT=1, fc on last step.
// R15: two independent 16-batch tiles per warp (32 batches/warp). The HMMA
// result latency (~230 cyc, measured via R13/R14 invariance) is hidden by
// interleaving the two tiles' MMAs and activations within one warp, since
// 512 full-tile warps < 592 SMSPs leaves no cross-warp cover. All 24 MMAs
// issue first, activations after. R13-style accumulation (hi/lo into same
// regs - proven free) keeps registers low. 128 blocks x 2 warps.

#define SEQ     512
#define HID     16
#define WPB     2
#define THREADS (WPB * 32)
#define BATCH   8192
#define BPW     32        // batches per warp: 2 tiles of 16

typedef unsigned int u32;

__device__ __forceinline__ float tanh_mufu(float v) {
    float r;
    asm("tanh.approx.f32 %0, %1;" : "=f"(r) : "f"(v));
    return r;
}
__device__ __forceinline__ u32 pack_h2(float a, float b) {
    __half2 h = __floats2half2_rn(a, b);
    return *reinterpret_cast<u32*>(&h);
}
__device__ __forceinline__ u32 pack_halves(__half a, __half b) {
    __half2 h = __halves2half2(a, b);
    return *reinterpret_cast<u32*>(&h);
}
// D += A @ B  (m16n8k16, f16 inputs, f32 accumulate)
__device__ __forceinline__ void mma16816(float& d0, float& d1, float& d2, float& d3,
                                         u32 a0, u32 a1, u32 a2, u32 a3,
                                         u32 b0, u32 b1) {
    asm("mma.sync.aligned.m16n8k16.row.col.f32.f16.f16.f32 "
        "{%0,%1,%2,%3}, {%4,%5,%6,%7}, {%8,%9}, {%0,%1,%2,%3};"
        : "+f"(d0), "+f"(d1), "+f"(d2), "+f"(d3)
        : "r"(a0), "r"(a1), "r"(a2), "r"(a3), "r"(b0), "r"(b1));
}

__global__ __launch_bounds__(THREADS)
void rnn2_kernel(const float* __restrict__ x,
                 const float* __restrict__ Wih0, const float* __restrict__ Whh0,
                 const float* __restrict__ bih0, const float* __restrict__ bhh0,
                 const float* __restrict__ Wih1, const float* __restrict__ Whh1,
                 const float* __restrict__ bih1, const float* __restrict__ bhh1,
                 const float* __restrict__ Wfc,  const float* __restrict__ bfc,
                 float* __restrict__ out)
{
    const int w    = threadIdx.x >> 5;
    const int lane = threadIdx.x & 31;
    const int g    = lane >> 2;      // group 0..7
    const int tg   = lane & 3;       // thread-in-group
    const int base = (blockIdx.x * WPB + w) * BPW;   // first batch of this warp

    // ---- B fragments (shared by both tiles): hi/lo split, col-major k16n8 ----
    u32 Bh0[2][2], Bl0[2][2];   // Whh0
    u32 Bh1[2][2], Bl1[2][2];   // Wih1
    u32 Bh2[2][2], Bl2[2][2];   // Whh1
    {
        const float* Ws[3] = { Whh0, Wih1, Whh1 };
        for (int m = 0; m < 3; m++) {
            for (int tau = 0; tau < 2; tau++) {
                int n = g + 8 * tau;
                const float* row = Ws[m] + n * HID;
                float w0 = row[2 * tg],     w1 = row[2 * tg + 1];
                float w2 = row[2 * tg + 8], w3 = row[2 * tg + 9];
                __half h0 = __float2half_rn(w0), h1 = __float2half_rn(w1);
                __half h2 = __float2half_rn(w2), h3 = __float2half_rn(w3);
                __half l0 = __float2half_rn(w0 - __half2float(h0));
                __half l1 = __float2half_rn(w1 - __half2float(h1));
                __half l2 = __float2half_rn(w2 - __half2float(h2));
                __half l3 = __float2half_rn(w3 - __half2float(h3));
                u32 bh0 = pack_halves(h0, h1), bh1 = pack_halves(h2, h3);
                u32 bl0 = pack_halves(l0, l1), bl1 = pack_halves(l2, l3);
                if (m == 0) { Bh0[tau][0] = bh0; Bh0[tau][1] = bh1; Bl0[tau][0] = bl0; Bl0[tau][1] = bl1; }
                if (m == 1) { Bh1[tau][0] = bh0; Bh1[tau][1] = bh1; Bl1[tau][0] = bl0; Bl1[tau][1] = bl1; }
                if (m == 2) { Bh2[tau][0] = bh0; Bh2[tau][1] = bh1; Bl2[tau][0] = bl0; Bl2[tau][1] = bl1; }
            }
        }
    }

    // per-lane column constants, j -> col {2tg, 2tg+1, 2tg+8, 2tg+9}
    float wi0c[4], c0c[4], c1c[4], wfcc[4];
    {
        int cols[4] = { 2 * tg, 2 * tg + 1, 2 * tg + 8, 2 * tg + 9 };
#pragma unroll
        for (int j = 0; j < 4; j++) {
            int c = cols[j];
            wi0c[j] = Wih0[c];
            c0c[j]  = bih0[c] + bhh0[c];
            c1c[j]  = bih1[c] + bhh1[c];
            wfcc[j] = Wfc[c];
        }
    }

    // x pointers: [tile][0]=row g, [tile][1]=row g+8
    const float* xp00 = x + (size_t)(base + g) * SEQ;
    const float* xp01 = x + (size_t)(base + g + 8) * SEQ;
    const float* xp10 = x + (size_t)(base + 16 + g) * SEQ;
    const float* xp11 = x + (size_t)(base + 16 + g + 8) * SEQ;

    // A fragments per tile; zero initial state
    u32 A00[4] = {0u,0u,0u,0u}, A01[4] = {0u,0u,0u,0u};   // tile0: h0, h1
    u32 A10[4] = {0u,0u,0u,0u}, A11[4] = {0u,0u,0u,0u};   // tile1: h0, h1

    // one substep for BOTH tiles. Phase A: all 24 MMAs. Phase B: activations.
    auto substep = [&](float x0g, float x0g8, float x1g, float x1g8, bool zero_h1) {
        float e0[8], f0[8], e1[8], f1[8];
        // layer0 init: wi0*x + bias  (rows g/g+8 -> regs {0,1}/{2,3} per n-tile)
        e0[0] = fmaf(wi0c[0], x0g,  c0c[0]);
        e0[1] = fmaf(wi0c[1], x0g,  c0c[1]);
        e0[2] = fmaf(wi0c[0], x0g8, c0c[0]);
        e0[3] = fmaf(wi0c[1], x0g8, c0c[1]);
        e0[4] = fmaf(wi0c[2], x0g,  c0c[2]);
        e0[5] = fmaf(wi0c[3], x0g,  c0c[3]);
        e0[6] = fmaf(wi0c[2], x0g8, c0c[2]);
        e0[7] = fmaf(wi0c[3], x0g8, c0c[3]);
        e1[0] = fmaf(wi0c[0], x1g,  c0c[0]);
        e1[1] = fmaf(wi0c[1], x1g,  c0c[1]);
        e1[2] = fmaf(wi0c[0], x1g8, c0c[0]);
        e1[3] = fmaf(wi0c[1], x1g8, c0c[1]);
        e1[4] = fmaf(wi0c[2], x1g,  c0c[2]);
        e1[5] = fmaf(wi0c[3], x1g,  c0c[3]);
        e1[6] = fmaf(wi0c[2], x1g8, c0c[2]);
        e1[7] = fmaf(wi0c[3], x1g8, c0c[3]);
        f0[0] = c1c[0]; f0[1] = c1c[1]; f0[2] = c1c[0]; f0[3] = c1c[1];
        f0[4] = c1c[2]; f0[5] = c1c[3]; f0[6] = c1c[2]; f0[7] = c1c[3];
        f1[0] = c1c[0]; f1[1] = c1c[1]; f1[2] = c1c[0]; f1[3] = c1c[1];
        f1[4] = c1c[2]; f1[5] = c1c[3]; f1[6] = c1c[2]; f1[7] = c1c[3];

        // --- phase A: all MMAs, tile-interleaved (hi/lo accumulate in-place) ---
        // e chains (layer 0)
        mma16816(e0[0], e0[1], e0[2], e0[3], A00[0], A00[1], A00[2], A00[3], Bh0[0][0], Bh0[0][1]);
        mma16816(e0[0], e0[1], e0[2], e0[3], A00[0], A00[1], A00[2], A00[3], Bl0[0][0], Bl0[0][1]);
        mma16816(e0[4], e0[5], e0[6], e0[7], A00[0], A00[1], A00[2], A00[3], Bh0[1][0], Bh0[1][1]);
        mma16816(e0[4], e0[5], e0[6], e0[7], A00[0], A00[1], A00[2], A00[3], Bl0[1][0], Bl0[1][1]);
        mma16816(e1[0], e1[1], e1[2], e1[3], A10[0], A10[1], A10[2], A10[3], Bh0[0][0], Bh0[0][1]);
        mma16816(e1[0], e1[1], e1[2], e1[3], A10[0], A10[1], A10[2], A10[3], Bl0[0][0], Bl0[0][1]);
        mma16816(e1[4], e1[5], e1[6], e1[7], A10[0], A10[1], A10[2], A10[3], Bh0[1][0], Bh0[1][1]);
        mma16816(e1[4], e1[5], e1[6], e1[7], A10[0], A10[1], A10[2], A10[3], Bl0[1][0], Bl0[1][1]);
        // f chains (layer 1): wih1(h0) + whh1(h1), hi+lo each
        mma16816(f0[0], f0[1], f0[2], f0[3], A00[0], A00[1], A00[2], A00[3], Bh1[0][0], Bh1[0][1]);
        mma16816(f0[0], f0[1], f0[2], f0[3], A00[0], A00[1], A00[2], A00[3], Bl1[0][0], Bl1[0][1]);
        mma16816(f0[0], f0[1], f0[2], f0[3], A01[0], A01[1], A01[2], A01[3], Bh2[0][0], Bh2[0][1]);
        mma16816(f0[0], f0[1], f0[2], f0[3], A01[0], A01[1], A01[2], A01[3], Bl2[0][0], Bl2[0][1]);
        mma16816(f0[4], f0[5], f0[6], f0[7], A00[0], A00[1], A00[2], A00[3], Bh1[1][0], Bh1[1][1]);
        mma16816(f0[4], f0[5], f0[6], f0[7], A00[0], A00[1], A00[2], A00[3], Bl1[1][0], Bl1[1][1]);
        mma16816(f0[4], f0[5], f0[6], f0[7], A01[0], A01[1], A01[2], A01[3], Bh2[1][0], Bh2[1][1]);
        mma16816(f0[4], f0[5], f0[6], f0[7], A01[0], A01[1], A01[2], A01[3], Bl2[1][0], Bl2[1][1]);
        mma16816(f1[0], f1[1], f1[2], f1[3], A10[0], A10[1], A10[2], A10[3], Bh1[0][0], Bh1[0][1]);
        mma16816(f1[0], f1[1], f1[2], f1[3], A10[0], A10[1], A10[2], A10[3], Bl1[0][0], Bl1[0][1]);
        mma16816(f1[0], f1[1], f1[2], f1[3], A11[0], A11[1], A11[2], A11[3], Bh2[0][0], Bh2[0][1]);
        mma16816(f1[0], f1[1], f1[2], f1[3], A11[0], A11[1], A11[2], A11[3], Bl2[0][0], Bl2[0][1]);
        mma16816(f1[4], f1[5], f1[6], f1[7], A10[0], A10[1], A10[2], A10[3], Bh1[1][0], Bh1[1][1]);
        mma16816(f1[4], f1[5], f1[6], f1[7], A10[0], A10[1], A10[2], A10[3], Bl1[1][0], Bl1[1][1]);
        mma16816(f1[4], f1[5], f1[6], f1[7], A11[0], A11[1], A11[2], A11[3], Bh2[1][0], Bh2[1][1]);
        mma16816(f1[4], f1[5], f1[6], f1[7], A11[0], A11[1], A11[2], A11[3], Bl2[1][0], Bl2[1][1]);

        // --- phase B: activations + repack (D layout == A layout per lane) ---
        A00[0] = pack_h2(tanh_mufu(e0[0]), tanh_mufu(e0[1]));
        A00[1] = pack_h2(tanh_mufu(e0[2]), tanh_mufu(e0[3]));
        A00[2] = pack_h2(tanh_mufu(e0[4]), tanh_mufu(e0[5]));
        A00[3] = pack_h2(tanh_mufu(e0[6]), tanh_mufu(e0[7]));
        A10[0] = pack_h2(tanh_mufu(e1[0]), tanh_mufu(e1[1]));
        A10[1] = pack_h2(tanh_mufu(e1[2]), tanh_mufu(e1[3]));
        A10[2] = pack_h2(tanh_mufu(e1[4]), tanh_mufu(e1[5]));
        A10[3] = pack_h2(tanh_mufu(e1[6]), tanh_mufu(e1[7]));
        if (zero_h1) {
            A01[0] = A01[1] = A01[2] = A01[3] = 0u;
            A11[0] = A11[1] = A11[2] = A11[3] = 0u;
        } else {
            A01[0] = pack_h2(tanh_mufu(f0[0]), tanh_mufu(f0[1]));
            A01[1] = pack_h2(tanh_mufu(f0[2]), tanh_mufu(f0[3]));
            A01[2] = pack_h2(tanh_mufu(f0[4]), tanh_mufu(f0[5]));
            A01[3] = pack_h2(tanh_mufu(f0[6]), tanh_mufu(f0[7]));
            A11[0] = pack_h2(tanh_mufu(f1[0]), tanh_mufu(f1[1]));
            A11[1] = pack_h2(tanh_mufu(f1[2]), tanh_mufu(f1[3]));
            A11[2] = pack_h2(tanh_mufu(f1[4]), tanh_mufu(f1[5]));
            A11[3] = pack_h2(tanh_mufu(f1[6]), tanh_mufu(f1[7]));
        }
    };

    float4 c00 = *(const float4*)xp00;
    float4 c01 = *(const float4*)xp01;
    float4 c10 = *(const float4*)xp10;
    float4 c11 = *(const float4*)xp11;

#pragma unroll 1
    for (int tc = 0; tc < SEQ; tc += 4) {
        int tn = (tc + 4 < SEQ) ? tc + 4 : (SEQ - 4);
        float4 n00 = *(const float4*)(xp00 + tn);
        float4 n01 = *(const float4*)(xp01 + tn);
        float4 n10 = *(const float4*)(xp10 + tn);
        float4 n11 = *(const float4*)(xp11 + tn);

        substep(c00.x, c01.x, c10.x, c11.x, tc == 0);
        substep(c00.y, c01.y, c10.y, c11.y, false);
        substep(c00.z, c01.z, c10.z, c11.z, false);
        substep(c00.w, c01.w, c10.w, c11.w, false);

        c00 = n00; c01 = n01; c10 = n10; c11 = n11;
    }

    // ---- epilogue per tile: h1(511) = tanh(Wih1 h0(511) + Whh1 h1(510) + c1) ----
    const float b0 = bfc[0];
#pragma unroll
    for (int T = 0; T < 2; T++) {
        const u32* A0 = (T == 0) ? A00 : A10;
        const u32* A1 = (T == 0) ? A01 : A11;
        float f[8];
        f[0] = c1c[0]; f[1] = c1c[1]; f[2] = c1c[0]; f[3] = c1c[1];
        f[4] = c1c[2]; f[5] = c1c[3]; f[6] = c1c[2]; f[7] = c1c[3];
        mma16816(f[0], f[1], f[2], f[3], A0[0], A0[1], A0[2], A0[3], Bh1[0][0], Bh1[0][1]);
        mma16816(f[0], f[1], f[2], f[3], A0[0], A0[1], A0[2], A0[3], Bl1[0][0], Bl1[0][1]);
        mma16816(f[0], f[1], f[2], f[3], A1[0], A1[1], A1[2], A1[3], Bh2[0][0], Bh2[0][1]);
        mma16816(f[0], f[1], f[2], f[3], A1[0], A1[1], A1[2], A1[3], Bl2[0][0], Bl2[0][1]);
        mma16816(f[4], f[5], f[6], f[7], A0[0], A0[1], A0[2], A0[3], Bh1[1][0], Bh1[1][1]);
        mma16816(f[4], f[5], f[6], f[7], A0[0], A0[1], A0[2], A0[3], Bl1[1][0], Bl1[1][1]);
        mma16816(f[4], f[5], f[6], f[7], A1[0], A1[1], A1[2], A1[3], Bh2[1][0], Bh2[1][1]);
        mma16816(f[4], f[5], f[6], f[7], A1[0], A1[1], A1[2], A1[3], Bl2[1][0], Bl2[1][1]);

        // fc: row g uses regs {0,1} + {4,5}; row g+8 uses {2,3} + {6,7}
        float pg  = wfcc[0] * tanh_mufu(f[0]) + wfcc[1] * tanh_mufu(f[1])
                  + wfcc[2] * tanh_mufu(f[4]) + wfcc[3] * tanh_mufu(f[5]);
        float pg8 = wfcc[0] * tanh_mufu(f[2]) + wfcc[1] * tanh_mufu(f[3])
                  + wfcc[2] * tanh_mufu(f[6]) + wfcc[3] * tanh_mufu(f[7]);
        pg  += __shfl_xor_sync(0xffffffffu, pg, 1, 4);
        pg8 += __shfl_xor_sync(0xffffffffu, pg8, 1, 4);
        pg  += __shfl_xor_sync(0xffffffffu, pg, 2, 4);
        pg8 += __shfl_xor_sync(0xffffffffu, pg8, 2, 4);
        if (tg == 0) {
            out[base + 16 * T + g]     = pg + b0;
            out[base + 16 * T + g + 8] = pg8 + b0;
        }
    }
}

extern "C" void kernel_launch(void* const* d_in, const int* in_sizes, int n_in,
                              void* d_out, int out_size)
{
    const float* x    = (const float*)d_in[0];
    const float* Wih0 = (const float*)d_in[1];
    const float* Whh0 = (const float*)d_in[2];
    const float* bih0 = (const float*)d_in[3];
    const float* bhh0 = (const float*)d_in[4];
    const float* Wih1 = (const float*)d_in[5];
    const float* Whh1 = (const float*)d_in[6];
    const float* bih1 = (const float*)d_in[7];
    const float* bhh1 = (const float*)d_in[8];
    const float* Wfc  = (const float*)d_in[9];
    const float* bfc  = (const float*)d_in[10];
    float* out = (float*)d_out;

    rnn2_kernel<<<BATCH / (WPB * BPW), THREADS>>>(x, Wih0, Whh0, bih0, bhh0,
                                                  Wih1, Whh1, bih1, bhh1,
                                                  Wfc, bfc, out);
}